// round 16
// baseline (speedup 1.0000x reference)
#include <cuda_runtime.h>
#include <cuda_bf16.h>

// ANFIS fuzzy inference, batch=2M rows x 4 features.
// out = sum_j(w_j * clip(conseq_j)) / max(sum_j w_j, 1e-8),
// w_j = prod of 4 Gaussian memberships.
//
// PDL 2-node shell + packed f32x2 body with TWO interleaved pairs per
// thread (4 rows/thread). R16 change: constants stored in __constant__
// ALREADY packed as u64 lane-pairs (ulonglong2 -> one LDC.128 delivers two
// ready f32x2 operands, ZERO pack MOVs):
//   ab2[11] : {.x=(a',a'), .y=(b',b')}
//   cq2[15] : {.x=(cq_m0,cq_m0), .y=(cq_m1,cq_m1)}  (group-permuted order)
// Each LDC is shared by both interleaved pairs (13 LDC.128 per pair).

namespace {
// Rules grouped by q = (ante2-6)*2 + (ante3-9); p = ante0*3 + (ante1-3).
// Verified against RULE_ANTECEDENTS.
__device__ constexpr int GRP_P[30]  = {0,3,1,2,8,5,7,  8,7,5,4,  0,4,3,6,5,
                                       0,1,3,2,8,  0,1,3,2,7,  0,1,3,4};
__device__ constexpr int GRP_CQ[30] = {9,13,15,19,23,27,28,  22,24,25,29,
                                       2,11,17,18,20,  4,10,12,14,26,
                                       0,3,6,7,21,  1,5,8,16};
__device__ constexpr int GRP_OF[30] = {0,0,0,0,0,0,0, 1,1,1,1, 2,2,2,2,2,
                                       3,3,3,3,3, 4,4,4,4,4, 5,5,5,5};
__device__ constexpr int DM[11] = {0,0,0,1,1,1,2,2,2,3,3};
}

using u64 = unsigned long long;

struct CstBlob {
    ulonglong2 ab2[11];   // .x=(a',a') .y=(b',b')   -> one LDC.128
    ulonglong2 cq2[15];   // .x=(cq2k,cq2k) .y=(cq2k+1,cq2k+1), permuted
};
__constant__ CstBlob g_cst;

__device__ __forceinline__ u64 pk2(float lo, float hi) {
    u64 r; asm("mov.b64 %0, {%1, %2};" : "=l"(r) : "f"(lo), "f"(hi)); return r;
}
__device__ __forceinline__ void upk2(u64 v, float& lo, float& hi) {
    asm("mov.b64 {%0, %1}, %2;" : "=f"(lo), "=f"(hi) : "l"(v));
}
__device__ __forceinline__ u64 fma2(u64 a, u64 b, u64 c) {
    u64 d; asm("fma.rn.f32x2 %0, %1, %2, %3;" : "=l"(d) : "l"(a), "l"(b), "l"(c)); return d;
}
__device__ __forceinline__ u64 mul2(u64 a, u64 b) {
    u64 d; asm("mul.rn.f32x2 %0, %1, %2;" : "=l"(d) : "l"(a), "l"(b)); return d;
}
__device__ __forceinline__ u64 add2(u64 a, u64 b) {
    u64 d; asm("add.rn.f32x2 %0, %1, %2;" : "=l"(d) : "l"(a), "l"(b)); return d;
}
__device__ __forceinline__ float ex2neg(float t) {
    float nt = __int_as_float(__float_as_int(t) ^ 0x80000000);
    float r; asm("ex2.approx.ftz.f32 %0, %1;" : "=f"(r) : "f"(nt)); return r;
}
__device__ __forceinline__ float ex2(float t) {
    float r; asm("ex2.approx.ftz.f32 %0, %1;" : "=f"(r) : "f"(t)); return r;
}
__device__ __forceinline__ u64 dupf(float v) {
    unsigned u = __float_as_uint(v);
    return ((u64)u << 32) | (u64)u;
}

__global__ void prep_kernel(const float* __restrict__ c,
                            const float* __restrict__ log_s,
                            const float* __restrict__ conseq,
                            CstBlob* __restrict__ cst)
{
    const int t = threadIdx.x;
    if (t < 11) {
        const float KS = 0.8493218002880191f;  // sqrt(0.5 * log2(e))
        float ci  = c[t];
        float sg  = fmaxf(__expf(log_s[t]), 0.001f);
        float ap  = KS / sg;
        float bp  = -ci * ap;
        cst->ab2[t] = make_ulonglong2(dupf(ap), dupf(bp));
    }
    if (t < 15) {
        float v0 = fminf(fmaxf(conseq[GRP_CQ[2 * t]], 0.0f), 100.0f);
        float v1 = fminf(fmaxf(conseq[GRP_CQ[2 * t + 1]], 0.0f), 100.0f);
        cst->cq2[t] = make_ulonglong2(dupf(v0), dupf(v1));
    }
    __threadfence();
#if __CUDA_ARCH__ >= 900
    cudaTriggerProgrammaticLaunchCompletion();
#endif
}

constexpr int THREADS = 128;
constexpr int ROWS_PER_THREAD = 4;   // two packed f32x2 pairs
constexpr int TILE = THREADS * ROWS_PER_THREAD;   // 512 rows/block

// Two interleaved packed pairs: shared constant LDC.128s, doubled ILP,
// zero constant-marshalling MOVs.
__device__ __forceinline__ void anfis_pair2(const u64 xp0[4], const u64 xp1[4],
                                            u64& res0, u64& res1)
{
    // Memberships; each ab2[i] LDC.128 serves both pairs directly.
    u64 mu0[11], mu1[11];
    #pragma unroll
    for (int i = 0; i < 11; i++) {
        ulonglong2 ab = g_cst.ab2[i];     // LDC.128: aa=ab.x, bb=ab.y
        u64 d0 = fma2(xp0[DM[i]], ab.x, ab.y);
        u64 d1 = fma2(xp1[DM[i]], ab.x, ab.y);
        u64 t0 = mul2(d0, d0);
        u64 t1 = mul2(d1, d1);
        float a0, b0, a1, b1;
        upk2(t0, a0, b0);
        upk2(t1, a1, b1);
        mu0[i] = pk2(ex2neg(a0), ex2neg(b0));
        mu1[i] = pk2(ex2neg(a1), ex2neg(b1));
    }

    // Pair products for both pairs.
    u64 Pv0[9], Qv0[6], Pv1[9], Qv1[6];
    #pragma unroll
    for (int i = 0; i < 3; i++)
        #pragma unroll
        for (int j = 0; j < 3; j++) {
            Pv0[i * 3 + j] = mul2(mu0[i], mu0[3 + j]);
            Pv1[i * 3 + j] = mul2(mu1[i], mu1[3 + j]);
        }
    #pragma unroll
    for (int i = 0; i < 3; i++)
        #pragma unroll
        for (int j = 0; j < 2; j++) {
            Qv0[i * 2 + j] = mul2(mu0[6 + i], mu0[9 + j]);
            Qv1[i * 2 + j] = mul2(mu1[6 + i], mu1[9 + j]);
        }

    // Weighted group inner sums; each cq2[k] LDC.128 serves 2 rules x 2 pairs.
    u64 s10[6], s11[6];
    #pragma unroll
    for (int g = 0; g < 6; g++) { s10[g] = 0ull; s11[g] = 0ull; }

    #pragma unroll
    for (int k = 0; k < 15; k++) {
        ulonglong2 C = g_cst.cq2[k];      // LDC.128: c0=C.x, c1=C.y
        const int m0 = 2 * k, m1 = 2 * k + 1;
        s10[GRP_OF[m0]] = fma2(Pv0[GRP_P[m0]], C.x, s10[GRP_OF[m0]]);
        s11[GRP_OF[m0]] = fma2(Pv1[GRP_P[m0]], C.x, s11[GRP_OF[m0]]);
        s10[GRP_OF[m1]] = fma2(Pv0[GRP_P[m1]], C.y, s10[GRP_OF[m1]]);
        s11[GRP_OF[m1]] = fma2(Pv1[GRP_P[m1]], C.y, s11[GRP_OF[m1]]);
    }

    // Unweighted group sums with CSE, both pairs.
    u64 u0 = add2(add2(Pv0[0], Pv0[1]), Pv0[3]);
    u64 v0 = add2(u0, Pv0[2]);
    u64 u1 = add2(add2(Pv1[0], Pv1[1]), Pv1[3]);
    u64 v1 = add2(u1, Pv1[2]);

    u64 s00_0 = add2(v0, add2(add2(Pv0[8], Pv0[5]), Pv0[7]));
    u64 s00_1 = add2(add2(Pv0[8], Pv0[7]), add2(Pv0[5], Pv0[4]));
    u64 s00_2 = add2(add2(add2(Pv0[0], Pv0[4]), add2(Pv0[3], Pv0[6])), Pv0[5]);
    u64 s00_3 = add2(v0, Pv0[8]);
    u64 s00_4 = add2(v0, Pv0[7]);
    u64 s00_5 = add2(u0, Pv0[4]);

    u64 s01_0 = add2(v1, add2(add2(Pv1[8], Pv1[5]), Pv1[7]));
    u64 s01_1 = add2(add2(Pv1[8], Pv1[7]), add2(Pv1[5], Pv1[4]));
    u64 s01_2 = add2(add2(add2(Pv1[0], Pv1[4]), add2(Pv1[3], Pv1[6])), Pv1[5]);
    u64 s01_3 = add2(v1, Pv1[8]);
    u64 s01_4 = add2(v1, Pv1[7]);
    u64 s01_5 = add2(u1, Pv1[4]);

    // Split accumulators, both pairs.
    u64 aA0 = mul2(Qv0[0], s10[0]);
    u64 aB0 = mul2(Qv0[1], s10[1]);
    u64 aA1 = mul2(Qv1[0], s11[0]);
    u64 aB1 = mul2(Qv1[1], s11[1]);
    aA0 = fma2(Qv0[2], s10[2], aA0);  aA1 = fma2(Qv1[2], s11[2], aA1);
    aB0 = fma2(Qv0[3], s10[3], aB0);  aB1 = fma2(Qv1[3], s11[3], aB1);
    aA0 = fma2(Qv0[4], s10[4], aA0);  aA1 = fma2(Qv1[4], s11[4], aA1);
    aB0 = fma2(Qv0[5], s10[5], aB0);  aB1 = fma2(Qv1[5], s11[5], aB1);

    u64 wA0 = mul2(Qv0[0], s00_0);
    u64 wB0 = mul2(Qv0[1], s00_1);
    u64 wA1 = mul2(Qv1[0], s01_0);
    u64 wB1 = mul2(Qv1[1], s01_1);
    wA0 = fma2(Qv0[2], s00_2, wA0);  wA1 = fma2(Qv1[2], s01_2, wA1);
    wB0 = fma2(Qv0[3], s00_3, wB0);  wB1 = fma2(Qv1[3], s01_3, wB1);
    wA0 = fma2(Qv0[4], s00_4, wA0);  wA1 = fma2(Qv1[4], s01_4, wA1);
    wB0 = fma2(Qv0[5], s00_5, wB0);  wB1 = fma2(Qv1[5], s01_5, wB1);

    u64 acc0  = add2(aA0, aB0);
    u64 wsum0 = add2(wA0, wB0);
    u64 acc1  = add2(aA1, aB1);
    u64 wsum1 = add2(wA1, wB1);

    float al0, ah0, wl0, wh0, al1, ah1, wl1, wh1;
    upk2(acc0, al0, ah0);  upk2(wsum0, wl0, wh0);
    upk2(acc1, al1, ah1);  upk2(wsum1, wl1, wh1);
    res0 = pk2(__fdividef(al0, fmaxf(wl0, 1e-8f)),
               __fdividef(ah0, fmaxf(wh0, 1e-8f)));
    res1 = pk2(__fdividef(al1, fmaxf(wl1, 1e-8f)),
               __fdividef(ah1, fmaxf(wh1, 1e-8f)));
}

// Scalar path for the tail tile. Lane-0 halves of the packed constants.
__device__ __forceinline__ float lane0(u64 v) {
    float lo, hi; upk2(v, lo, hi); return lo;
}

__device__ __forceinline__ float anfis_row_scalar(const float4 xv)
{
    const float xd[4] = {xv.x, xv.y, xv.z, xv.w};
    float mu[11];
    #pragma unroll
    for (int i = 0; i < 11; i++) {
        ulonglong2 ab = g_cst.ab2[i];
        float d = fmaf(xd[DM[i]], lane0(ab.x), lane0(ab.y));
        mu[i] = ex2(-d * d);
    }
    float Pv[9], Qv[6];
    #pragma unroll
    for (int i = 0; i < 3; i++)
        #pragma unroll
        for (int j = 0; j < 3; j++)
            Pv[i * 3 + j] = mu[i] * mu[3 + j];
    #pragma unroll
    for (int i = 0; i < 3; i++)
        #pragma unroll
        for (int j = 0; j < 2; j++)
            Qv[i * 2 + j] = mu[6 + i] * mu[9 + j];

    float s1[6];
    #pragma unroll
    for (int g = 0; g < 6; g++) s1[g] = 0.0f;
    #pragma unroll
    for (int k = 0; k < 15; k++) {
        ulonglong2 C = g_cst.cq2[k];
        const int m0 = 2 * k, m1 = 2 * k + 1;
        s1[GRP_OF[m0]] = fmaf(Pv[GRP_P[m0]], lane0(C.x), s1[GRP_OF[m0]]);
        s1[GRP_OF[m1]] = fmaf(Pv[GRP_P[m1]], lane0(C.y), s1[GRP_OF[m1]]);
    }

    float u = (Pv[0] + Pv[1]) + Pv[3];
    float v = u + Pv[2];
    float s0_0 = v + ((Pv[8] + Pv[5]) + Pv[7]);
    float s0_1 = (Pv[8] + Pv[7]) + (Pv[5] + Pv[4]);
    float s0_2 = ((Pv[0] + Pv[4]) + (Pv[3] + Pv[6])) + Pv[5];
    float s0_3 = v + Pv[8];
    float s0_4 = v + Pv[7];
    float s0_5 = u + Pv[4];

    float accA = Qv[0] * s1[0];
    float accB = Qv[1] * s1[1];
    accA = fmaf(Qv[2], s1[2], accA);
    accB = fmaf(Qv[3], s1[3], accB);
    accA = fmaf(Qv[4], s1[4], accA);
    accB = fmaf(Qv[5], s1[5], accB);

    float wsA = Qv[0] * s0_0;
    float wsB = Qv[1] * s0_1;
    wsA = fmaf(Qv[2], s0_2, wsA);
    wsB = fmaf(Qv[3], s0_3, wsB);
    wsA = fmaf(Qv[4], s0_4, wsA);
    wsB = fmaf(Qv[5], s0_5, wsB);

    return __fdividef(accA + accB, fmaxf(wsA + wsB, 1e-8f));
}

__global__ void __launch_bounds__(THREADS)
anfis_kernel(const float4* __restrict__ x,
             float* __restrict__ out,
             int n)
{
    const int base = blockIdx.x * TILE + threadIdx.x;
    const bool full = (blockIdx.x * TILE + TILE <= n);

    if (full) {
        // Prefetch all 4 rows BEFORE the dependency sync (independent of prep).
        float4 v0 = __ldg(x + base);
        float4 v1 = __ldg(x + base + THREADS);
        float4 v2 = __ldg(x + base + 2 * THREADS);
        float4 v3 = __ldg(x + base + 3 * THREADS);

#if __CUDA_ARCH__ >= 900
        cudaGridDependencySynchronize();
#endif

        u64 xp0[4] = { pk2(v0.x, v1.x), pk2(v0.y, v1.y),
                       pk2(v0.z, v1.z), pk2(v0.w, v1.w) };
        u64 xp1[4] = { pk2(v2.x, v3.x), pk2(v2.y, v3.y),
                       pk2(v2.z, v3.z), pk2(v2.w, v3.w) };

        u64 r0, r1;
        anfis_pair2(xp0, xp1, r0, r1);

        float o0, o1, o2, o3;
        upk2(r0, o0, o1);
        upk2(r1, o2, o3);
        out[base]               = o0;
        out[base + THREADS]     = o1;
        out[base + 2 * THREADS] = o2;
        out[base + 3 * THREADS] = o3;
    } else {
#if __CUDA_ARCH__ >= 900
        cudaGridDependencySynchronize();
#endif
        #pragma unroll
        for (int k = 0; k < ROWS_PER_THREAD; k++) {
            int r = base + k * THREADS;
            if (r < n) {
                float4 xv = __ldg(x + r);
                out[r] = anfis_row_scalar(xv);
            }
        }
    }
}

extern "C" void kernel_launch(void* const* d_in, const int* in_sizes, int n_in,
                              void* d_out, int out_size)
{
    const float* x      = (const float*)d_in[0];
    const float* c      = (const float*)d_in[1];
    const float* log_s  = (const float*)d_in[2];
    const float* conseq = (const float*)d_in[3];
    float* out          = (float*)d_out;

    int n = in_sizes[0] / 4;   // rows
    int blocks = (n + TILE - 1) / TILE;

    void* cst_ptr = nullptr;
    cudaGetSymbolAddress(&cst_ptr, g_cst);

    // Node 1: prep (PDL trigger).
    prep_kernel<<<1, 32>>>(c, log_s, conseq, (CstBlob*)cst_ptr);

    // Node 2: main kernel with programmatic dependent launch.
    cudaLaunchConfig_t cfg = {};
    cfg.gridDim  = dim3((unsigned)blocks, 1, 1);
    cfg.blockDim = dim3(THREADS, 1, 1);
    cfg.dynamicSmemBytes = 0;
    cfg.stream = 0;
    cudaLaunchAttribute attrs[1];
    attrs[0].id = cudaLaunchAttributeProgrammaticStreamSerialization;
    attrs[0].val.programmaticStreamSerializationAllowed = 1;
    cfg.attrs = attrs;
    cfg.numAttrs = 1;

    cudaError_t err = cudaLaunchKernelEx(&cfg, anfis_kernel,
                                         (const float4*)x, out, n);
    if (err != cudaSuccess) {
        anfis_kernel<<<blocks, THREADS>>>((const float4*)x, out, n);
    }
}

// round 17
// speedup vs baseline: 1.0078x; 1.0078x over previous
#include <cuda_runtime.h>
#include <cuda_bf16.h>

// ANFIS fuzzy inference, batch=2M rows x 4 features. SINGLE kernel node.
// out = sum_j(w_j * clip(conseq_j)) / max(sum_j w_j, 1e-8),
// w_j = prod of 4 Gaussian memberships.
//
// Structure:
//  - Each block computes the 52 preprocessed constants into smem, packed as
//    ulonglong2 lane-pairs (a'=(1/sigma)*sqrt(0.5*log2 e), b'=-c*a',
//    cq clipped and PERMUTED into group order). ~100 issues, latency hidden
//    by co-resident CTAs and the prefetched x rows.
//  - Body consumes constants via asm volatile ld.shared.v2.u64 (LDS.128):
//    unhoistable by ptxas -> transient registers, LDC-like economics, no
//    second graph node. 13 vector loads per thread, each shared by both
//    interleaved pairs.
//  - Packed f32x2 body, TWO interleaved pairs per thread (4 rows/thread),
//    validated in R14-R16: pair-product CSE, group factorization over the
//    6 shared Q factors, CSE'd unweighted sums, split accumulators.
//  - 128-thread blocks.

namespace {
// Rules grouped by q = (ante2-6)*2 + (ante3-9); p = ante0*3 + (ante1-3).
// Verified against RULE_ANTECEDENTS.
__device__ constexpr int GRP_P[30]  = {0,3,1,2,8,5,7,  8,7,5,4,  0,4,3,6,5,
                                       0,1,3,2,8,  0,1,3,2,7,  0,1,3,4};
__device__ constexpr int GRP_CQ[30] = {9,13,15,19,23,27,28,  22,24,25,29,
                                       2,11,17,18,20,  4,10,12,14,26,
                                       0,3,6,7,21,  1,5,8,16};
__device__ constexpr int GRP_OF[30] = {0,0,0,0,0,0,0, 1,1,1,1, 2,2,2,2,2,
                                       3,3,3,3,3, 4,4,4,4,4, 5,5,5,5};
__device__ constexpr int DM[11] = {0,0,0,1,1,1,2,2,2,3,3};
}

using u64 = unsigned long long;

__device__ __forceinline__ u64 pk2(float lo, float hi) {
    u64 r; asm("mov.b64 %0, {%1, %2};" : "=l"(r) : "f"(lo), "f"(hi)); return r;
}
__device__ __forceinline__ void upk2(u64 v, float& lo, float& hi) {
    asm("mov.b64 {%0, %1}, %2;" : "=f"(lo), "=f"(hi) : "l"(v));
}
__device__ __forceinline__ u64 fma2(u64 a, u64 b, u64 c) {
    u64 d; asm("fma.rn.f32x2 %0, %1, %2, %3;" : "=l"(d) : "l"(a), "l"(b), "l"(c)); return d;
}
__device__ __forceinline__ u64 mul2(u64 a, u64 b) {
    u64 d; asm("mul.rn.f32x2 %0, %1, %2;" : "=l"(d) : "l"(a), "l"(b)); return d;
}
__device__ __forceinline__ u64 add2(u64 a, u64 b) {
    u64 d; asm("add.rn.f32x2 %0, %1, %2;" : "=l"(d) : "l"(a), "l"(b)); return d;
}
__device__ __forceinline__ float ex2neg(float t) {
    float nt = __int_as_float(__float_as_int(t) ^ 0x80000000);
    float r; asm("ex2.approx.ftz.f32 %0, %1;" : "=f"(r) : "f"(nt)); return r;
}
__device__ __forceinline__ float ex2(float t) {
    float r; asm("ex2.approx.ftz.f32 %0, %1;" : "=f"(r) : "f"(t)); return r;
}
__device__ __forceinline__ u64 dupf(float v) {
    unsigned u = __float_as_uint(v);
    return ((u64)u << 32) | (u64)u;
}
__device__ __forceinline__ unsigned smem_u32(const void* p) {
    unsigned a;
    asm("{ .reg .u64 t; cvta.to.shared.u64 t, %1; cvt.u32.u64 %0, t; }"
        : "=r"(a) : "l"(p));
    return a;
}
// Unhoistable 16-byte shared load: two ready f32x2 operands, transient regs.
__device__ __forceinline__ void lds128(unsigned addr, u64& lo, u64& hi) {
    asm volatile("ld.shared.v2.u64 {%0, %1}, [%2];"
                 : "=l"(lo), "=l"(hi) : "r"(addr));
}
__device__ __forceinline__ float lane0(u64 v) {
    float lo, hi; upk2(v, lo, hi); return lo;
}

constexpr int THREADS = 128;
constexpr int ROWS_PER_THREAD = 4;   // two packed f32x2 pairs
constexpr int TILE = THREADS * ROWS_PER_THREAD;   // 512 rows/block

struct SmemConsts {
    ulonglong2 ab[11];   // .x=(a',a') .y=(b',b')
    ulonglong2 cq[15];   // .x=(cq_m0,cq_m0) .y=(cq_m1,cq_m1), permuted
};

// Two interleaved packed pairs; constants via asm LDS.128, shared by pairs.
__device__ __forceinline__ void anfis_pair2(const u64 xp0[4], const u64 xp1[4],
                                            unsigned ab_addr, unsigned cq_addr,
                                            u64& res0, u64& res1)
{
    // Memberships.
    u64 mu0[11], mu1[11];
    #pragma unroll
    for (int i = 0; i < 11; i++) {
        u64 aa, bb;
        lds128(ab_addr + i * 16, aa, bb);
        u64 d0 = fma2(xp0[DM[i]], aa, bb);
        u64 d1 = fma2(xp1[DM[i]], aa, bb);
        u64 t0 = mul2(d0, d0);
        u64 t1 = mul2(d1, d1);
        float a0, b0, a1, b1;
        upk2(t0, a0, b0);
        upk2(t1, a1, b1);
        mu0[i] = pk2(ex2neg(a0), ex2neg(b0));
        mu1[i] = pk2(ex2neg(a1), ex2neg(b1));
    }

    // Pair products.
    u64 Pv0[9], Qv0[6], Pv1[9], Qv1[6];
    #pragma unroll
    for (int i = 0; i < 3; i++)
        #pragma unroll
        for (int j = 0; j < 3; j++) {
            Pv0[i * 3 + j] = mul2(mu0[i], mu0[3 + j]);
            Pv1[i * 3 + j] = mul2(mu1[i], mu1[3 + j]);
        }
    #pragma unroll
    for (int i = 0; i < 3; i++)
        #pragma unroll
        for (int j = 0; j < 2; j++) {
            Qv0[i * 2 + j] = mul2(mu0[6 + i], mu0[9 + j]);
            Qv1[i * 2 + j] = mul2(mu1[6 + i], mu1[9 + j]);
        }

    // Weighted group inner sums; each LDS.128 serves 2 rules x 2 pairs.
    u64 s10[6], s11[6];
    #pragma unroll
    for (int g = 0; g < 6; g++) { s10[g] = 0ull; s11[g] = 0ull; }

    #pragma unroll
    for (int k = 0; k < 15; k++) {
        u64 c0, c1;
        lds128(cq_addr + k * 16, c0, c1);
        const int m0 = 2 * k, m1 = 2 * k + 1;
        s10[GRP_OF[m0]] = fma2(Pv0[GRP_P[m0]], c0, s10[GRP_OF[m0]]);
        s11[GRP_OF[m0]] = fma2(Pv1[GRP_P[m0]], c0, s11[GRP_OF[m0]]);
        s10[GRP_OF[m1]] = fma2(Pv0[GRP_P[m1]], c1, s10[GRP_OF[m1]]);
        s11[GRP_OF[m1]] = fma2(Pv1[GRP_P[m1]], c1, s11[GRP_OF[m1]]);
    }

    // Unweighted group sums with CSE, both pairs.
    u64 u0 = add2(add2(Pv0[0], Pv0[1]), Pv0[3]);
    u64 v0 = add2(u0, Pv0[2]);
    u64 u1 = add2(add2(Pv1[0], Pv1[1]), Pv1[3]);
    u64 v1 = add2(u1, Pv1[2]);

    u64 s00_0 = add2(v0, add2(add2(Pv0[8], Pv0[5]), Pv0[7]));
    u64 s00_1 = add2(add2(Pv0[8], Pv0[7]), add2(Pv0[5], Pv0[4]));
    u64 s00_2 = add2(add2(add2(Pv0[0], Pv0[4]), add2(Pv0[3], Pv0[6])), Pv0[5]);
    u64 s00_3 = add2(v0, Pv0[8]);
    u64 s00_4 = add2(v0, Pv0[7]);
    u64 s00_5 = add2(u0, Pv0[4]);

    u64 s01_0 = add2(v1, add2(add2(Pv1[8], Pv1[5]), Pv1[7]));
    u64 s01_1 = add2(add2(Pv1[8], Pv1[7]), add2(Pv1[5], Pv1[4]));
    u64 s01_2 = add2(add2(add2(Pv1[0], Pv1[4]), add2(Pv1[3], Pv1[6])), Pv1[5]);
    u64 s01_3 = add2(v1, Pv1[8]);
    u64 s01_4 = add2(v1, Pv1[7]);
    u64 s01_5 = add2(u1, Pv1[4]);

    // Split accumulators, both pairs.
    u64 aA0 = mul2(Qv0[0], s10[0]);
    u64 aB0 = mul2(Qv0[1], s10[1]);
    u64 aA1 = mul2(Qv1[0], s11[0]);
    u64 aB1 = mul2(Qv1[1], s11[1]);
    aA0 = fma2(Qv0[2], s10[2], aA0);  aA1 = fma2(Qv1[2], s11[2], aA1);
    aB0 = fma2(Qv0[3], s10[3], aB0);  aB1 = fma2(Qv1[3], s11[3], aB1);
    aA0 = fma2(Qv0[4], s10[4], aA0);  aA1 = fma2(Qv1[4], s11[4], aA1);
    aB0 = fma2(Qv0[5], s10[5], aB0);  aB1 = fma2(Qv1[5], s11[5], aB1);

    u64 wA0 = mul2(Qv0[0], s00_0);
    u64 wB0 = mul2(Qv0[1], s00_1);
    u64 wA1 = mul2(Qv1[0], s01_0);
    u64 wB1 = mul2(Qv1[1], s01_1);
    wA0 = fma2(Qv0[2], s00_2, wA0);  wA1 = fma2(Qv1[2], s01_2, wA1);
    wB0 = fma2(Qv0[3], s00_3, wB0);  wB1 = fma2(Qv1[3], s01_3, wB1);
    wA0 = fma2(Qv0[4], s00_4, wA0);  wA1 = fma2(Qv1[4], s01_4, wA1);
    wB0 = fma2(Qv0[5], s00_5, wB0);  wB1 = fma2(Qv1[5], s01_5, wB1);

    u64 acc0  = add2(aA0, aB0);
    u64 wsum0 = add2(wA0, wB0);
    u64 acc1  = add2(aA1, aB1);
    u64 wsum1 = add2(wA1, wB1);

    float al0, ah0, wl0, wh0, al1, ah1, wl1, wh1;
    upk2(acc0, al0, ah0);  upk2(wsum0, wl0, wh0);
    upk2(acc1, al1, ah1);  upk2(wsum1, wl1, wh1);
    res0 = pk2(__fdividef(al0, fmaxf(wl0, 1e-8f)),
               __fdividef(ah0, fmaxf(wh0, 1e-8f)));
    res1 = pk2(__fdividef(al1, fmaxf(wl1, 1e-8f)),
               __fdividef(ah1, fmaxf(wh1, 1e-8f)));
}

// Scalar path for the tail tile (lane-0 halves of packed constants).
__device__ __forceinline__ float anfis_row_scalar(const float4 xv,
                                                  unsigned ab_addr,
                                                  unsigned cq_addr)
{
    const float xd[4] = {xv.x, xv.y, xv.z, xv.w};
    float mu[11];
    #pragma unroll
    for (int i = 0; i < 11; i++) {
        u64 aa, bb;
        lds128(ab_addr + i * 16, aa, bb);
        float d = fmaf(xd[DM[i]], lane0(aa), lane0(bb));
        mu[i] = ex2(-d * d);
    }
    float Pv[9], Qv[6];
    #pragma unroll
    for (int i = 0; i < 3; i++)
        #pragma unroll
        for (int j = 0; j < 3; j++)
            Pv[i * 3 + j] = mu[i] * mu[3 + j];
    #pragma unroll
    for (int i = 0; i < 3; i++)
        #pragma unroll
        for (int j = 0; j < 2; j++)
            Qv[i * 2 + j] = mu[6 + i] * mu[9 + j];

    float s1[6];
    #pragma unroll
    for (int g = 0; g < 6; g++) s1[g] = 0.0f;
    #pragma unroll
    for (int k = 0; k < 15; k++) {
        u64 c0, c1;
        lds128(cq_addr + k * 16, c0, c1);
        const int m0 = 2 * k, m1 = 2 * k + 1;
        s1[GRP_OF[m0]] = fmaf(Pv[GRP_P[m0]], lane0(c0), s1[GRP_OF[m0]]);
        s1[GRP_OF[m1]] = fmaf(Pv[GRP_P[m1]], lane0(c1), s1[GRP_OF[m1]]);
    }

    float u = (Pv[0] + Pv[1]) + Pv[3];
    float v = u + Pv[2];
    float s0_0 = v + ((Pv[8] + Pv[5]) + Pv[7]);
    float s0_1 = (Pv[8] + Pv[7]) + (Pv[5] + Pv[4]);
    float s0_2 = ((Pv[0] + Pv[4]) + (Pv[3] + Pv[6])) + Pv[5];
    float s0_3 = v + Pv[8];
    float s0_4 = v + Pv[7];
    float s0_5 = u + Pv[4];

    float accA = Qv[0] * s1[0];
    float accB = Qv[1] * s1[1];
    accA = fmaf(Qv[2], s1[2], accA);
    accB = fmaf(Qv[3], s1[3], accB);
    accA = fmaf(Qv[4], s1[4], accA);
    accB = fmaf(Qv[5], s1[5], accB);

    float wsA = Qv[0] * s0_0;
    float wsB = Qv[1] * s0_1;
    wsA = fmaf(Qv[2], s0_2, wsA);
    wsB = fmaf(Qv[3], s0_3, wsB);
    wsA = fmaf(Qv[4], s0_4, wsA);
    wsB = fmaf(Qv[5], s0_5, wsB);

    return __fdividef(accA + accB, fmaxf(wsA + wsB, 1e-8f));
}

__global__ void __launch_bounds__(THREADS)
anfis_kernel(const float4* __restrict__ x,
             const float*  __restrict__ c,
             const float*  __restrict__ log_s,
             const float*  __restrict__ conseq,
             float* __restrict__ out,
             int n)
{
    __shared__ SmemConsts sm;

    const int t = threadIdx.x;
    const int base = blockIdx.x * TILE + t;
    const bool full = (blockIdx.x * TILE + TILE <= n);

    // Prefetch x rows FIRST — hides DRAM latency under the prep + barrier.
    float4 v0, v1, v2, v3;
    if (full) {
        v0 = __ldg(x + base);
        v1 = __ldg(x + base + THREADS);
        v2 = __ldg(x + base + 2 * THREADS);
        v3 = __ldg(x + base + 3 * THREADS);
    }

    // Per-block constant prep (~100 issues; latency overlapped).
    if (t < 11) {
        const float KS = 0.8493218002880191f;  // sqrt(0.5 * log2(e))
        float ci  = __ldg(c + t);
        float sg  = fmaxf(__expf(__ldg(log_s + t)), 0.001f);
        float ap  = KS / sg;
        sm.ab[t] = make_ulonglong2(dupf(ap), dupf(-ci * ap));
    }
    if (t < 15) {
        float q0 = fminf(fmaxf(__ldg(conseq + GRP_CQ[2 * t]), 0.0f), 100.0f);
        float q1 = fminf(fmaxf(__ldg(conseq + GRP_CQ[2 * t + 1]), 0.0f), 100.0f);
        sm.cq[t] = make_ulonglong2(dupf(q0), dupf(q1));
    }
    __syncthreads();

    const unsigned ab_addr = smem_u32(&sm.ab[0]);
    const unsigned cq_addr = smem_u32(&sm.cq[0]);

    if (full) {
        u64 xp0[4] = { pk2(v0.x, v1.x), pk2(v0.y, v1.y),
                       pk2(v0.z, v1.z), pk2(v0.w, v1.w) };
        u64 xp1[4] = { pk2(v2.x, v3.x), pk2(v2.y, v3.y),
                       pk2(v2.z, v3.z), pk2(v2.w, v3.w) };

        u64 r0, r1;
        anfis_pair2(xp0, xp1, ab_addr, cq_addr, r0, r1);

        float o0, o1, o2, o3;
        upk2(r0, o0, o1);
        upk2(r1, o2, o3);
        out[base]               = o0;
        out[base + THREADS]     = o1;
        out[base + 2 * THREADS] = o2;
        out[base + 3 * THREADS] = o3;
    } else {
        #pragma unroll
        for (int k = 0; k < ROWS_PER_THREAD; k++) {
            int r = base + k * THREADS;
            if (r < n) {
                float4 xv = __ldg(x + r);
                out[r] = anfis_row_scalar(xv, ab_addr, cq_addr);
            }
        }
    }
}

extern "C" void kernel_launch(void* const* d_in, const int* in_sizes, int n_in,
                              void* d_out, int out_size)
{
    const float* x      = (const float*)d_in[0];
    const float* c      = (const float*)d_in[1];
    const float* log_s  = (const float*)d_in[2];
    const float* conseq = (const float*)d_in[3];
    float* out          = (float*)d_out;

    int n = in_sizes[0] / 4;   // rows
    int blocks = (n + TILE - 1) / TILE;

    anfis_kernel<<<blocks, THREADS>>>((const float4*)x, c, log_s, conseq, out, n);
}